// round 13
// baseline (speedup 1.0000x reference)
#include <cuda_runtime.h>
#include <cuda_fp16.h>
#include <cstdint>

#define SEQL 2048
#define BATCH 2
#define HIDD 1024
#define NH 16
#define DHD 64
#define NR 101

// fp16 scratch (static __device__ — allocation-free)
__device__ __align__(16) __half g_Qp[BATCH*NH*SEQL*DHD];   // d-permuted
__device__ __align__(16) __half g_Kp[BATCH*NH*SEQL*DHD];   // d-permuted
__device__ __align__(16) __half g_Vp[BATCH*NH*SEQL*DHD];   // plain d
__device__ __align__(16) __half g_Ctx[BATCH*SEQL*HIDD];    // hid-permuted
__device__ __align__(16) __half g_XhQ[SEQL*BATCH*HIDD];
__device__ __align__(16) __half g_XhK[SEQL*BATCH*HIDD];
__device__ __align__(16) __half g_XhV[SEQL*BATCH*HIDD];
__device__ __align__(16) __half g_WhQ[HIDD*HIDD];
__device__ __align__(16) __half g_WhK[HIDD*HIDD];
__device__ __align__(16) __half g_WhV[HIDD*HIDD];
__device__ __align__(16) __half g_WhO[HIDD*HIDD];

__device__ __forceinline__ void mma_f16(float* c, const unsigned* a, const unsigned* b) {
    asm volatile(
        "mma.sync.aligned.m16n8k16.row.col.f32.f16.f16.f32 "
        "{%0,%1,%2,%3}, {%4,%5,%6,%7}, {%8,%9}, {%0,%1,%2,%3};"
        : "+f"(c[0]), "+f"(c[1]), "+f"(c[2]), "+f"(c[3])
        : "r"(a[0]), "r"(a[1]), "r"(a[2]), "r"(a[3]), "r"(b[0]), "r"(b[1]));
}
__device__ __forceinline__ void ldsm_x4_trans(unsigned& r0, unsigned& r1,
                                              unsigned& r2, unsigned& r3, uint32_t addr) {
    asm volatile("ldmatrix.sync.aligned.m8n8.x4.trans.shared.b16 {%0,%1,%2,%3}, [%4];"
                 : "=r"(r0), "=r"(r1), "=r"(r2), "=r"(r3) : "r"(addr));
}
__device__ __forceinline__ uint32_t s2u(const void* p) {
    uint32_t a;
    asm("{ .reg .u64 t; cvta.to.shared.u64 t, %1; cvt.u32.u64 %0, t; }" : "=r"(a) : "l"(p));
    return a;
}
// 8B-chunk swizzle selector for packed 32B rows
__device__ __forceinline__ int sws(int row) {
    return (((row >> 2) & 1) << 1) | ((row >> 3) & 1);
}
__device__ __forceinline__ uint4 swap64(uint4 v) {
    uint4 r; r.x = v.z; r.y = v.w; r.z = v.x; r.w = v.y; return r;
}

// ---------------------------------------------------------------------------
// Pre-pass: fp32 -> fp16, permuting half2 units within each 16-elem k-group
// as (u0,u4,u1,u5,u2,u6,u3,u7) so mma fragment pairs are address-adjacent.
// ---------------------------------------------------------------------------
__global__ __launch_bounds__(256) void preh(
    const float* __restrict__ q, const float* __restrict__ k, const float* __restrict__ v,
    const float* __restrict__ wq, const float* __restrict__ wk,
    const float* __restrict__ wv, const float* __restrict__ wo)
{
    const float* src; __half* dst; int n16;
    switch (blockIdx.y) {
        case 0: src = q;  dst = g_XhQ; n16 = SEQL*BATCH*HIDD/16; break;
        case 1: src = k;  dst = g_XhK; n16 = SEQL*BATCH*HIDD/16; break;
        case 2: src = v;  dst = g_XhV; n16 = SEQL*BATCH*HIDD/16; break;
        case 3: src = wq; dst = g_WhQ; n16 = HIDD*HIDD/16; break;
        case 4: src = wk; dst = g_WhK; n16 = HIDD*HIDD/16; break;
        case 5: src = wv; dst = g_WhV; n16 = HIDD*HIDD/16; break;
        default: src = wo; dst = g_WhO; n16 = HIDD*HIDD/16; break;
    }
    int g = blockIdx.x * 256 + threadIdx.x;
    if (g >= n16) return;
    const float4* p = (const float4*)(src + (size_t)g * 16);
    float4 x0 = p[0], x1 = p[1], x2 = p[2], x3 = p[3];
    __half2 u0 = __floats2half2_rn(x0.x, x0.y), u1 = __floats2half2_rn(x0.z, x0.w);
    __half2 u2 = __floats2half2_rn(x1.x, x1.y), u3 = __floats2half2_rn(x1.z, x1.w);
    __half2 u4 = __floats2half2_rn(x2.x, x2.y), u5 = __floats2half2_rn(x2.z, x2.w);
    __half2 u6 = __floats2half2_rn(x3.x, x3.y), u7 = __floats2half2_rn(x3.z, x3.w);
    __half2* d = (__half2*)(dst + (size_t)g * 16);
    d[0] = u0; d[1] = u4; d[2] = u1; d[3] = u5;
    d[4] = u2; d[5] = u6; d[6] = u3; d[7] = u7;
}

// ---------------------------------------------------------------------------
// fp16 GEMM m16n8k16: 128 thr, 4 warps (2m x 2n), warp 64x64, tile 128x128,
// BK=16 double-buffered. Packed 32B rows + 8B-chunk XOR swizzle:
// frag LDS.64 and fill STS.128 both provably bank-conflict-free.
// mode 0: V -> head layout plain d; mode 1: Q/K -> head layout d-permuted;
// mode 2: out-proj fp32 seq-first.
// ---------------------------------------------------------------------------
__device__ __forceinline__ void gemm_body(
    const __half* __restrict__ A, const __half* __restrict__ W,
    const float* __restrict__ bias, void* __restrict__ outv, int mode)
{
    __shared__ __half As[2][128*16];
    __shared__ __half Bs[2][128*16];
    const int tid = threadIdx.x, lane = tid & 31, warp = tid >> 5;
    const int grp = lane >> 2, l4 = lane & 3;
    const int wm = (warp >> 1) * 64, wn = (warp & 1) * 64;
    const int m0 = blockIdx.x * 128, n0 = blockIdx.y * 128;
    float acc[4][8][4];
    #pragma unroll
    for (int i = 0; i < 4; i++)
        #pragma unroll
        for (int j = 0; j < 8; j++)
            #pragma unroll
            for (int r = 0; r < 4; r++) acc[i][j][r] = 0.f;

    const __half *apt, *bpt;
    {
        int m = m0 + tid;
        if (mode < 2) { int b = m >> 11, l = m & 2047; apt = A + (size_t)(l*BATCH+b)*HIDD; }
        else          { apt = A + (size_t)m*HIDD; }
        bpt = W + (size_t)(n0 + tid)*HIDD;
    }
    uint4 va0 = *(const uint4*)apt, va1 = *(const uint4*)(apt + 8);
    uint4 vb0 = *(const uint4*)bpt, vb1 = *(const uint4*)(bpt + 8);

    const int sF  = sws(tid);
    const int oF0 = (sF >> 1) * 8;          // 16B slot for chunks {0,1}
    const int oF1 = 8 - oF0;                // slot for chunks {2,3}
    auto sts = [&](int buf) {
        uint4 a0 = va0, a1 = va1, b0 = vb0, b1 = vb1;
        if (sF & 1) { a0 = swap64(a0); a1 = swap64(a1); b0 = swap64(b0); b1 = swap64(b1); }
        *(uint4*)&As[buf][tid*16 + oF0] = a0;
        *(uint4*)&As[buf][tid*16 + oF1] = a1;
        *(uint4*)&Bs[buf][tid*16 + oF0] = b0;
        *(uint4*)&Bs[buf][tid*16 + oF1] = b1;
    };
    sts(0);
    __syncthreads();

    int cur = 0;
    for (int kt = 0; kt < 64; kt++) {
        if (kt + 1 < 64) {
            const __half* ap = apt + (kt+1)*16;
            const __half* bp = bpt + (kt+1)*16;
            va0 = *(const uint4*)ap; va1 = *(const uint4*)(ap + 8);
            vb0 = *(const uint4*)bp; vb1 = *(const uint4*)(bp + 8);
        }
        const __half* as = As[cur]; const __half* bs = Bs[cur];
        unsigned af[4][4], bf[8][2];
        #pragma unroll
        for (int i = 0; i < 4; i++) {
            int r0 = wm + i*16 + grp, r1 = r0 + 8;
            uint2 t0 = *(const uint2*)&as[r0*16 + ((l4 ^ sws(r0)) << 2)];
            uint2 t1 = *(const uint2*)&as[r1*16 + ((l4 ^ sws(r1)) << 2)];
            af[i][0] = t0.x; af[i][1] = t1.x; af[i][2] = t0.y; af[i][3] = t1.y;
        }
        #pragma unroll
        for (int j = 0; j < 8; j++) {
            int nn = wn + j*8 + grp;
            uint2 tb = *(const uint2*)&bs[nn*16 + ((l4 ^ sws(nn)) << 2)];
            bf[j][0] = tb.x; bf[j][1] = tb.y;
        }
        #pragma unroll
        for (int i = 0; i < 4; i++)
            #pragma unroll
            for (int j = 0; j < 8; j++)
                mma_f16(acc[i][j], af[i], bf[j]);
        if (kt + 1 < 64) sts(cur ^ 1);
        __syncthreads();
        cur ^= 1;
    }

    #pragma unroll
    for (int i = 0; i < 4; i++) {
        #pragma unroll
        for (int j = 0; j < 8; j++) {
            int col = n0 + wn + j*8 + l4*2;
            float b0v = bias[col], b1v = bias[col+1];
            #pragma unroll
            for (int pr = 0; pr < 2; pr++) {
                int rw = m0 + wm + i*16 + grp + pr*8;
                int b = rw >> 11, l = rw & 2047;
                float v0 = acc[i][j][pr*2+0] + b0v;
                float v1 = acc[i][j][pr*2+1] + b1v;
                if (mode == 2) {
                    float* p = (float*)outv + (size_t)(l*BATCH+b)*HIDD + col;
                    p[0] = v0; p[1] = v1;
                } else {
                    int h = col >> 6;
                    __half* p = (__half*)outv + ((size_t)(b*NH+h)*SEQL + l)*DHD;
                    int d;
                    if (mode == 1) {
                        int g16 = (col & 63) >> 4;
                        int pp = (j & 1) ? 2*l4 + 1 : 2*l4;
                        d = g16*16 + 2*pp;
                    } else d = col & 63;
                    *(__half2*)(p + d) = __floats2half2_rn(v0, v1);
                }
            }
        }
    }
}

__global__ __launch_bounds__(128, 2) void gemm_qkv(
    const float* __restrict__ bq, const float* __restrict__ bk, const float* __restrict__ bv)
{
    if (blockIdx.z == 0)      gemm_body(g_XhQ, g_WhQ, bq, g_Qp, 1);
    else if (blockIdx.z == 1) gemm_body(g_XhK, g_WhK, bk, g_Kp, 1);
    else                      gemm_body(g_XhV, g_WhV, bv, g_Vp, 0);
}

__global__ __launch_bounds__(128, 2) void gemm_out_h(
    const float* __restrict__ bo, float* __restrict__ out)
{
    gemm_body(g_Ctx, g_WhO, bo, out, 2);
}

// ---------------------------------------------------------------------------
// fp16 flash relative-attention: 128 thr (4 warps), q-tile 128 (warp: 32 rows,
// 2 row-groups), k-tiles 64, one-pass. P lives in dead Q region (no mid sync).
// K frags + ldsm'd V frags amortized over 2 row-groups. 2 CTAs/SM.
// (strides 80/72 halfs verified conflict-free — unchanged from R11)
// ---------------------------------------------------------------------------
#define AQS 80
#define AVS 72
#define OFFQ 0              // Q [128][80]; later P [128][80]
#define OFFK 10240          // relk [104][80] / K tile [64][80] / relv [101][64]
#define OFFV 18560          // V [64][72]
#define OFFQD 23168         // QD [128][104] fp16
#define OFFBD 36480         // band [128][100] fp16
#define ATT_SMEM_BYTES (49280*2)
#define C8 0.18033688011112042f   // 0.125 * log2(e)

__global__ __launch_bounds__(128, 2) void attn_h(
    const float* __restrict__ rel_k, const float* __restrict__ rel_v)
{
    extern __shared__ __half sm16[];
    const uint32_t smb = s2u(sm16);
    __half* qdp = sm16 + OFFQD;
    __half* pbd = sm16 + OFFBD;
    const int tid = threadIdx.x;
    const int lane = tid & 31, w = tid >> 5;
    const int grp = lane >> 2, l4 = lane & 3;
    const int bh = blockIdx.y;
    const int q0 = blockIdx.x * 128;
    const size_t base = (size_t)bh * SEQL * DHD;
    int rl[2][2];
    #pragma unroll
    for (int i = 0; i < 2; i++)
        #pragma unroll
        for (int hh = 0; hh < 2; hh++) rl[i][hh] = w*32 + i*16 + hh*8 + grp;

    // Q tile fill (fp16, d-permuted): 128 rows
    #pragma unroll
    for (int s = 0; s < 8; s++) {
        int idx = tid + s*128; int r = idx >> 3, c8 = (idx & 7)*8;
        *(uint4*)&sm16[OFFQ + r*AQS + c8] =
            *(const uint4*)(g_Qp + base + (size_t)(q0+r)*DHD + c8);
    }
    // rel_k rows 0..103 (zero-pad), fp32 -> fp16 permuted scatter
    #pragma unroll
    for (int s = 0; s < 13; s++) {
        int i = tid + s*128;
        if (i < 104*16) {
            int r = i >> 4, c4 = (i & 15)*4;
            float4 v = make_float4(0.f,0.f,0.f,0.f);
            if (r < NR) v = *(const float4*)(rel_k + r*DHD + c4);
            int g16 = c4 & ~15;
            int u0 = (c4 & 15) >> 1;          // 0,2,4,6
            int p0 = (u0 < 4) ? 2*u0 : 2*(u0-4)+1;
            int p1 = (u0+1 < 4) ? 2*(u0+1) : 2*(u0+1-4)+1;
            __half2* dst = (__half2*)&sm16[OFFK + r*AQS + g16];
            dst[p0] = __floats2half2_rn(v.x, v.y);
            dst[p1] = __floats2half2_rn(v.z, v.w);
        }
    }
    __syncthreads();

    // persistent Q fragments (2 row-groups)
    unsigned qf[2][4][4];
    #pragma unroll
    for (int i = 0; i < 2; i++)
        #pragma unroll
        for (int c = 0; c < 4; c++) {
            uint2 t0 = *(const uint2*)&sm16[OFFQ + rl[i][0]*AQS + c*16 + 4*l4];
            uint2 t1 = *(const uint2*)&sm16[OFFQ + rl[i][1]*AQS + c*16 + 4*l4];
            qf[i][c][0] = t0.x; qf[i][c][1] = t1.x;
            qf[i][c][2] = t0.y; qf[i][c][3] = t1.y;
        }
    // qdot = Q . rel_k -> fp16 QD table [128][104]
    #pragma unroll
    for (int j = 0; j < 13; j++) {
        float c4a[2][4];
        #pragma unroll
        for (int i = 0; i < 2; i++)
            #pragma unroll
            for (int r = 0; r < 4; r++) c4a[i][r] = 0.f;
        #pragma unroll
        for (int c = 0; c < 4; c++) {
            uint2 tb = *(const uint2*)&sm16[OFFK + (j*8+grp)*AQS + c*16 + 4*l4];
            unsigned bf2[2] = {tb.x, tb.y};
            mma_f16(c4a[0], qf[0][c], bf2);
            mma_f16(c4a[1], qf[1][c], bf2);
        }
        int col = j*8 + l4*2;
        #pragma unroll
        for (int i = 0; i < 2; i++) {
            *(__half2*)&qdp[rl[i][0]*104 + col] = __floats2half2_rn(c4a[i][0], c4a[i][1]);
            *(__half2*)&qdp[rl[i][1]*104 + col] = __floats2half2_rn(c4a[i][2], c4a[i][3]);
        }
    }
    __syncthreads();

    // zero band [128][100] halfs = 6400 words
    {
        unsigned* bw = (unsigned*)pbd;
        #pragma unroll
        for (int s = 0; s < 50; s++) bw[tid + s*128] = 0u;
    }
    float qlC[2][2], qrC[2][2];
    #pragma unroll
    for (int i = 0; i < 2; i++)
        #pragma unroll
        for (int hh = 0; hh < 2; hh++) {
            qlC[i][hh] = __half2float(qdp[rl[i][hh]*104 + 0])   * C8;
            qrC[i][hh] = __half2float(qdp[rl[i][hh]*104 + 100]) * C8;
        }
    __syncthreads();

    float oacc[2][8][4];
    #pragma unroll
    for (int i = 0; i < 2; i++)
        #pragma unroll
        for (int j = 0; j < 8; j++)
            #pragma unroll
            for (int r = 0; r < 4; r++) oacc[i][j][r] = 0.f;
    float lft[2][2] = {{0.f,0.f},{0.f,0.f}}, rgt[2][2] = {{0.f,0.f},{0.f,0.f}};

    uint4 kreg[4], vreg[4];
    #pragma unroll
    for (int s = 0; s < 4; s++) {
        int idx = tid + s*128; int r = idx >> 3, c8 = (idx & 7)*8;
        kreg[s] = *(const uint4*)(g_Kp + base + (size_t)r*DHD + c8);
        vreg[s] = *(const uint4*)(g_Vp + base + (size_t)r*DHD + c8);
    }

    for (int kt = 0; kt < 32; kt++) {
        const int k0 = kt * 64;
        #pragma unroll
        for (int s = 0; s < 4; s++) {
            int idx = tid + s*128; int r = idx >> 3, c8 = (idx & 7)*8;
            *(uint4*)&sm16[OFFK + r*AQS + c8] = kreg[s];
            *(uint4*)&sm16[OFFV + r*AVS + c8] = vreg[s];
        }
        __syncthreads();
        if (kt + 1 < 32) {
            #pragma unroll
            for (int s = 0; s < 4; s++) {
                int idx = tid + s*128; int r = idx >> 3, c8 = (idx & 7)*8;
                size_t g = base + (size_t)(k0 + 64 + r)*DHD + c8;
                kreg[s] = *(const uint4*)(g_Kp + g);
                vreg[s] = *(const uint4*)(g_Vp + g);
            }
        }

        const int dq = k0 - q0;
        const bool nearT = (dq >= -64 && dq <= 128);
        const bool leftT = dq < 0;

        // S = Q K^T per j-tile; exp + classify; store P into OFFQ (warp rows)
        #pragma unroll
        for (int j = 0; j < 8; j++) {
            float sfr[2][4];
            #pragma unroll
            for (int i = 0; i < 2; i++)
                #pragma unroll
                for (int r = 0; r < 4; r++) sfr[i][r] = 0.f;
            #pragma unroll
            for (int c = 0; c < 4; c++) {
                uint2 tb = *(const uint2*)&sm16[OFFK + (j*8+grp)*AQS + c*16 + 4*l4];
                unsigned bf2[2] = {tb.x, tb.y};
                mma_f16(sfr[0], qf[0][c], bf2);
                mma_f16(sfr[1], qf[1][c], bf2);
            }
            const int po = (j>>1)*16 + ((j&1) ? 4*l4+2 : 4*l4);
            if (nearT) {
                #pragma unroll
                for (int i = 0; i < 2; i++)
                    #pragma unroll
                    for (int hh = 0; hh < 2; hh++) {
                        int rr = rl[i][hh];
                        float pp[2];
                        #pragma unroll
                        for (int par = 0; par < 2; par++) {
                            int col = j*8 + l4*2 + par;
                            int dlt = k0 + col - (q0 + rr);
                            int ix = min(max(dlt, -50), 50) + 50;
                            float qd = __half2float(qdp[rr*104 + ix]);
                            float pv = exp2f((sfr[i][hh*2+par] + qd) * C8);
                            if (dlt <= -50)     lft[i][hh] += pv;
                            else if (dlt >= 50) rgt[i][hh] += pv;
                            else pbd[rr*100 + dlt + 49] = __float2half(pv);
                            pp[par] = pv;
                        }
                        *(__half2*)&sm16[OFFQ + rr*AQS + po] = __floats2half2_rn(pp[0], pp[1]);
                    }
            } else {
                #pragma unroll
                for (int i = 0; i < 2; i++)
                    #pragma unroll
                    for (int hh = 0; hh < 2; hh++) {
                        int rr = rl[i][hh];
                        float qc = leftT ? qlC[i][hh] : qrC[i][hh];
                        float pv0 = exp2f(fmaf(sfr[i][hh*2+0], C8, qc));
                        float pv1 = exp2f(fmaf(sfr[i][hh*2+1], C8, qc));
                        if (leftT) lft[i][hh] += pv0 + pv1;
                        else       rgt[i][hh] += pv0 + pv1;
                        *(__half2*)&sm16[OFFQ + rr*AQS + po] = __floats2half2_rn(pv0, pv1);
                    }
            }
        }
        __syncwarp();

        // O += P V : A-frags from P (OFFQ), ldsm V B-frags shared across i
        #pragma unroll
        for (int c = 0; c < 4; c++) {
            unsigned af[2][4];
            #pragma unroll
            for (int i = 0; i < 2; i++) {
                uint2 t0 = *(const uint2*)&sm16[OFFQ + rl[i][0]*AQS + c*16 + 4*l4];
                uint2 t1 = *(const uint2*)&sm16[OFFQ + rl[i][1]*AQS + c*16 + 4*l4];
                af[i][0] = t0.x; af[i][1] = t1.x; af[i][2] = t0.y; af[i][3] = t1.y;
            }
            #pragma unroll
            for (int jj = 0; jj < 8; jj += 2) {
                unsigned r0, r1, r2, r3;
                int mm = lane >> 3, rs = lane & 7;
                uint32_t ad = smb + 2u*(OFFV + (c*16 + (mm&1)*8 + rs)*AVS + (jj + (mm>>1))*8);
                ldsm_x4_trans(r0, r1, r2, r3, ad);
                unsigned b0[2] = {r0, r1}, b1[2] = {r2, r3};
                mma_f16(oacc[0][jj],   af[0], b0);
                mma_f16(oacc[0][jj+1], af[0], b1);
                mma_f16(oacc[1][jj],   af[1], b0);
                mma_f16(oacc[1][jj+1], af[1], b1);
            }
        }
        __syncthreads();
    }

    // quad-reduce clip masses
    #pragma unroll
    for (int i = 0; i < 2; i++)
        #pragma unroll
        for (int hh = 0; hh < 2; hh++) {
            lft[i][hh] += __shfl_xor_sync(0xffffffffu, lft[i][hh], 1);
            lft[i][hh] += __shfl_xor_sync(0xffffffffu, lft[i][hh], 2);
            rgt[i][hh] += __shfl_xor_sync(0xffffffffu, rgt[i][hh], 1);
            rgt[i][hh] += __shfl_xor_sync(0xffffffffu, rgt[i][hh], 2);
        }

    // rel_v fp16 plain [101][64] into dead K region
    #pragma unroll
    for (int s = 0; s < 13; s++) {
        int i = tid + s*128;
        if (i < NR*16) {
            int r = i >> 4, c4 = (i & 15)*4;
            float4 v = *(const float4*)(rel_v + r*DHD + c4);
            __half2* dst = (__half2*)&sm16[OFFK + r*64 + c4];
            dst[0] = __floats2half2_rn(v.x, v.y);
            dst[1] = __floats2half2_rn(v.z, v.w);
        }
    }
    __syncthreads();

    float w2a[2][8][4];
    #pragma unroll
    for (int i = 0; i < 2; i++)
        #pragma unroll
        for (int j = 0; j < 8; j++)
            #pragma unroll
            for (int r = 0; r < 4; r++) w2a[i][j][r] = 0.f;
    float bsum[2][2] = {{0.f,0.f},{0.f,0.f}};
    for (int bnd = 0; bnd < 99; bnd++) {
        float pv[2][2];
        #pragma unroll
        for (int i = 0; i < 2; i++)
            #pragma unroll
            for (int hh = 0; hh < 2; hh++) {
                pv[i][hh] = __half2float(pbd[rl[i][hh]*100 + bnd]);
                bsum[i][hh] += pv[i][hh];
            }
        const __half* rv = &sm16[OFFK + (bnd+1)*64 + l4*2];
        #pragma unroll
        for (int j = 0; j < 8; j++) {
            float2 rr = __half22float2(*(const __half2*)&rv[j*8]);
            #pragma unroll
            for (int i = 0; i < 2; i++) {
                w2a[i][j][0] += pv[i][0]*rr.x; w2a[i][j][1] += pv[i][0]*rr.y;
                w2a[i][j][2] += pv[i][1]*rr.x; w2a[i][j][3] += pv[i][1]*rr.y;
            }
        }
    }
    {
        const __half* rvL = &sm16[OFFK + 0*64   + l4*2];
        const __half* rvR = &sm16[OFFK + 100*64 + l4*2];
        #pragma unroll
        for (int j = 0; j < 8; j++) {
            float2 L = __half22float2(*(const __half2*)&rvL[j*8]);
            float2 R = __half22float2(*(const __half2*)&rvR[j*8]);
            #pragma unroll
            for (int i = 0; i < 2; i++) {
                w2a[i][j][0] += lft[i][0]*L.x + rgt[i][0]*R.x;
                w2a[i][j][1] += lft[i][0]*L.y + rgt[i][0]*R.y;
                w2a[i][j][2] += lft[i][1]*L.x + rgt[i][1]*R.x;
                w2a[i][j][3] += lft[i][1]*L.y + rgt[i][1]*R.y;
            }
        }
    }

    // Ctx: fp16 hid-permuted for gemm_out fast path
    const int b = bh / NH, h = bh % NH;
    float inv[2][2];
    #pragma unroll
    for (int i = 0; i < 2; i++)
        #pragma unroll
        for (int hh = 0; hh < 2; hh++)
            inv[i][hh] = 1.f / (lft[i][hh] + rgt[i][hh] + bsum[i][hh]);
    #pragma unroll
    for (int i = 0; i < 2; i++)
        #pragma unroll
        for (int j = 0; j < 8; j++) {
            int pp = (j & 1) ? 2*l4 + 1 : 2*l4;
            int dcol = (j>>1)*16 + 2*pp;
            size_t o0 = ((size_t)(b*SEQL + q0 + rl[i][0]))*HIDD + h*DHD + dcol;
            size_t o1 = ((size_t)(b*SEQL + q0 + rl[i][1]))*HIDD + h*DHD + dcol;
            *(__half2*)&g_Ctx[o0] = __floats2half2_rn((oacc[i][j][0] + w2a[i][j][0]) * inv[i][0],
                                                      (oacc[i][j][1] + w2a[i][j][1]) * inv[i][0]);
            *(__half2*)&g_Ctx[o1] = __floats2half2_rn((oacc[i][j][2] + w2a[i][j][2]) * inv[i][1],
                                                      (oacc[i][j][3] + w2a[i][j][3]) * inv[i][1]);
        }
}

// ---------------------------------------------------------------------------
extern "C" void kernel_launch(void* const* d_in, const int* in_sizes, int n_in,
                              void* d_out, int out_size)
{
    const float* query = (const float*)d_in[0];
    const float* key   = (const float*)d_in[1];
    const float* value = (const float*)d_in[2];
    const float* Wq    = (const float*)d_in[3];
    const float* bq    = (const float*)d_in[4];
    const float* Wk    = (const float*)d_in[5];
    const float* bk    = (const float*)d_in[6];
    const float* Wv    = (const float*)d_in[7];
    const float* bv    = (const float*)d_in[8];
    const float* Wo    = (const float*)d_in[9];
    const float* bo    = (const float*)d_in[10];
    const float* rel_k = (const float*)d_in[11];
    const float* rel_v = (const float*)d_in[12];
    float* out = (float*)d_out;

    dim3 gp((SEQL*BATCH*HIDD/16 + 255)/256, 7);
    preh<<<gp, 256>>>(query, key, value, Wq, Wk, Wv, Wo);

    dim3 gq(32, 8, 3);
    gemm_qkv<<<gq, 128>>>(bq, bk, bv);

    cudaFuncSetAttribute(attn_h, cudaFuncAttributeMaxDynamicSharedMemorySize,
                         ATT_SMEM_BYTES);
    dim3 ga(SEQL / 128, BATCH * NH);
    attn_h<<<ga, 128, ATT_SMEM_BYTES>>>(rel_k, rel_v);

    dim3 gg(32, 8);
    gemm_out_h<<<gg, 128>>>(bo, out);
}

// round 16
// speedup vs baseline: 1.3093x; 1.3093x over previous
#include <cuda_runtime.h>
#include <cuda_fp16.h>
#include <cstdint>

#define SEQL 2048
#define BATCH 2
#define HIDD 1024
#define NH 16
#define DHD 64
#define NR 101

// fp16 scratch (static __device__ — allocation-free)
__device__ __align__(16) __half g_Qp[BATCH*NH*SEQL*DHD];   // d-permuted (attn conv)
__device__ __align__(16) __half g_Kp[BATCH*NH*SEQL*DHD];   // d-permuted
__device__ __align__(16) __half g_Vp[BATCH*NH*SEQL*DHD];   // plain d
__device__ __align__(16) __half g_Ctx[BATCH*SEQL*HIDD];    // plain (canonical)
__device__ __align__(16) __half g_XhQ[SEQL*BATCH*HIDD];
__device__ __align__(16) __half g_XhK[SEQL*BATCH*HIDD];
__device__ __align__(16) __half g_XhV[SEQL*BATCH*HIDD];
__device__ __align__(16) __half g_WhQ[HIDD*HIDD];
__device__ __align__(16) __half g_WhK[HIDD*HIDD];
__device__ __align__(16) __half g_WhV[HIDD*HIDD];
__device__ __align__(16) __half g_WhO[HIDD*HIDD];

__device__ __forceinline__ void mma_f16(float* c, const unsigned* a, const unsigned* b) {
    asm volatile(
        "mma.sync.aligned.m16n8k16.row.col.f32.f16.f16.f32 "
        "{%0,%1,%2,%3}, {%4,%5,%6,%7}, {%8,%9}, {%0,%1,%2,%3};"
        : "+f"(c[0]), "+f"(c[1]), "+f"(c[2]), "+f"(c[3])
        : "r"(a[0]), "r"(a[1]), "r"(a[2]), "r"(a[3]), "r"(b[0]), "r"(b[1]));
}
__device__ __forceinline__ void ldsm_x4(unsigned* r, uint32_t addr) {
    asm volatile("ldmatrix.sync.aligned.m8n8.x4.shared.b16 {%0,%1,%2,%3}, [%4];"
                 : "=r"(r[0]), "=r"(r[1]), "=r"(r[2]), "=r"(r[3]) : "r"(addr));
}
__device__ __forceinline__ void ldsm_x4_trans(unsigned& r0, unsigned& r1,
                                              unsigned& r2, unsigned& r3, uint32_t addr) {
    asm volatile("ldmatrix.sync.aligned.m8n8.x4.trans.shared.b16 {%0,%1,%2,%3}, [%4];"
                 : "=r"(r0), "=r"(r1), "=r"(r2), "=r"(r3) : "r"(addr));
}
__device__ __forceinline__ uint32_t s2u(const void* p) {
    uint32_t a;
    asm("{ .reg .u64 t; cvta.to.shared.u64 t, %1; cvt.u32.u64 %0, t; }" : "=r"(a) : "l"(p));
    return a;
}
__device__ __forceinline__ void cpa16(uint32_t s, const void* g) {
    asm volatile("cp.async.cg.shared.global [%0], [%1], 16;" :: "r"(s), "l"(g));
}
__device__ __forceinline__ void cpa_commit() {
    asm volatile("cp.async.commit_group;" ::: "memory");
}
template <int N>
__device__ __forceinline__ void cpa_wait() {
    asm volatile("cp.async.wait_group %0;" :: "n"(N) : "memory");
}

// ---------------------------------------------------------------------------
// Pre-pass: plain fp32 -> fp16 convert (canonical k-major for ldmatrix GEMM).
// ---------------------------------------------------------------------------
__global__ __launch_bounds__(256) void preh(
    const float* __restrict__ q, const float* __restrict__ k, const float* __restrict__ v,
    const float* __restrict__ wq, const float* __restrict__ wk,
    const float* __restrict__ wv, const float* __restrict__ wo)
{
    const float* src; __half* dst; int n8;
    switch (blockIdx.y) {
        case 0: src = q;  dst = g_XhQ; n8 = SEQL*BATCH*HIDD/8; break;
        case 1: src = k;  dst = g_XhK; n8 = SEQL*BATCH*HIDD/8; break;
        case 2: src = v;  dst = g_XhV; n8 = SEQL*BATCH*HIDD/8; break;
        case 3: src = wq; dst = g_WhQ; n8 = HIDD*HIDD/8; break;
        case 4: src = wk; dst = g_WhK; n8 = HIDD*HIDD/8; break;
        case 5: src = wv; dst = g_WhV; n8 = HIDD*HIDD/8; break;
        default: src = wo; dst = g_WhO; n8 = HIDD*HIDD/8; break;
    }
    int g = blockIdx.x * 256 + threadIdx.x;
    if (g >= n8) return;
    const float4* p = (const float4*)(src + (size_t)g * 8);
    float4 x0 = p[0], x1 = p[1];
    __half2* d = (__half2*)(dst + (size_t)g * 8);
    d[0] = __floats2half2_rn(x0.x, x0.y);
    d[1] = __floats2half2_rn(x0.z, x0.w);
    d[2] = __floats2half2_rn(x1.x, x1.y);
    d[3] = __floats2half2_rn(x1.z, x1.w);
}

// ---------------------------------------------------------------------------
// fp16 GEMM m16n8k16: 256 thr, 8 warps (2m x 4n), warp 64x32, tile 128x128,
// BK=32, cp.async 3-stage pipeline, ldmatrix.x4 fragments.
// smem row = 32 halfs (64B); chunk swizzle c' = c ^ ((r>>1)&3)  (16B chunks).
// mode 0: V -> head layout plain d; mode 1: Q/K -> head layout d-permuted;
// mode 2: out-proj fp32 seq-first.
// ---------------------------------------------------------------------------
#define STG_HALFS 8192      // per stage: A 4096 + B 4096 halfs (16 KB)

__device__ __forceinline__ void gemm_body(
    const __half* __restrict__ A, const __half* __restrict__ W,
    const float* __restrict__ bias, void* __restrict__ outv, int mode)
{
    __shared__ __align__(16) __half sm[3*STG_HALFS];   // 48 KB
    const uint32_t smb = s2u(sm);
    const int tid = threadIdx.x, lane = tid & 31, warp = tid >> 5;
    const int grp = lane >> 2, l4 = lane & 3;
    const int wm = (warp >> 2) * 64, wn = (warp & 3) * 32;
    const int m0 = blockIdx.x * 128, n0 = blockIdx.y * 128;

    float acc[4][4][4];
    #pragma unroll
    for (int i = 0; i < 4; i++)
        #pragma unroll
        for (int j = 0; j < 4; j++)
            #pragma unroll
            for (int r = 0; r < 4; r++) acc[i][j][r] = 0.f;

    // ---- fill setup: thread covers A rows (tid>>2, 64+tid>>2) chunk tid&3 ----
    const int fr0 = tid >> 2, fr1 = 64 + (tid >> 2), fc = tid & 3;
    const __half *aptr0, *aptr1;
    if (mode < 2) {
        int m = m0 + fr0, b = m >> 11, l = m & 2047;
        aptr0 = A + (size_t)(l*BATCH+b)*HIDD + fc*8;
        m = m0 + fr1; b = m >> 11; l = m & 2047;
        aptr1 = A + (size_t)(l*BATCH+b)*HIDD + fc*8;
    } else {
        aptr0 = A + (size_t)(m0+fr0)*HIDD + fc*8;
        aptr1 = A + (size_t)(m0+fr1)*HIDD + fc*8;
    }
    const __half* bptr0 = W + (size_t)(n0+fr0)*HIDD + fc*8;
    const __half* bptr1 = W + (size_t)(n0+fr1)*HIDD + fc*8;
    const int dA0 = fr0*32 + ((fc ^ (fr0>>1)) & 3)*8;
    const int dA1 = fr1*32 + ((fc ^ (fr1>>1)) & 3)*8;
    const int dB0 = 4096 + dA0;       // B rows share fr indices
    const int dB1 = 4096 + dA1;

    auto fill = [&](int st, int ko) {
        uint32_t base = smb + (uint32_t)(st*STG_HALFS)*2u;
        cpa16(base + dA0*2, aptr0 + ko);
        cpa16(base + dA1*2, aptr1 + ko);
        cpa16(base + dB0*2, bptr0 + ko);
        cpa16(base + dB1*2, bptr1 + ko);
    };

    // ---- fragment address constants (halfs) ----
    int offA[4][2], offB[4];
    {
        int lane7 = lane & 7;
        int cAb = (lane >> 4) & 1;       // extra k8 within kstep
        #pragma unroll
        for (int i = 0; i < 4; i++) {
            int r = wm + i*16 + lane7 + ((lane & 8) ? 8 : 0);
            int sw = (r >> 1) & 3;
            offA[i][0] = r*32 + (((0*2 + cAb) ^ sw) & 3)*8;
            offA[i][1] = r*32 + (((1*2 + cAb) ^ sw) & 3)*8;
        }
        int cB = lane >> 3;              // 0..3 (k chunks)
        #pragma unroll
        for (int j = 0; j < 4; j++) {
            int r = wn + j*8 + lane7;
            offB[j] = 4096 + r*32 + ((cB ^ ((r >> 1) & 3)) & 3)*8;
        }
    }

    fill(0, 0); cpa_commit();
    fill(1, 32); cpa_commit();

    int st = 0;
    for (int kt = 0; kt < 32; kt++) {
        cpa_wait<1>();
        __syncthreads();
        if (kt + 2 < 32) {
            int st2 = st + 2; if (st2 >= 3) st2 -= 3;
            fill(st2, (kt + 2) * 32);
        }
        cpa_commit();

        uint32_t base = smb + (uint32_t)(st*STG_HALFS)*2u;
        unsigned bfr[4][4];
        #pragma unroll
        for (int j = 0; j < 4; j++) ldsm_x4(bfr[j], base + offB[j]*2);
        #pragma unroll
        for (int ks = 0; ks < 2; ks++) {
            unsigned afr[4][4];
            #pragma unroll
            for (int i = 0; i < 4; i++) ldsm_x4(afr[i], base + offA[i][ks]*2);
            #pragma unroll
            for (int i = 0; i < 4; i++)
                #pragma unroll
                for (int j = 0; j < 4; j++) {
                    unsigned bf2[2] = {bfr[j][ks*2], bfr[j][ks*2+1]};
                    mma_f16(acc[i][j], afr[i], bf2);
                }
        }
        __syncthreads();
        st = st + 1 == 3 ? 0 : st + 1;
    }

    // ---- epilogue (same conventions as before) ----
    #pragma unroll
    for (int i = 0; i < 4; i++) {
        #pragma unroll
        for (int j = 0; j < 4; j++) {
            int col = n0 + wn + j*8 + l4*2;
            float b0v = bias[col], b1v = bias[col+1];
            #pragma unroll
            for (int pr = 0; pr < 2; pr++) {
                int rw = m0 + wm + i*16 + grp + pr*8;
                int b = rw >> 11, l = rw & 2047;
                float v0 = acc[i][j][pr*2+0] + b0v;
                float v1 = acc[i][j][pr*2+1] + b1v;
                if (mode == 2) {
                    float* p = (float*)outv + (size_t)(l*BATCH+b)*HIDD + col;
                    p[0] = v0; p[1] = v1;
                } else {
                    int h = col >> 6;
                    __half* p = (__half*)outv + ((size_t)(b*NH+h)*SEQL + l)*DHD;
                    int d;
                    if (mode == 1) {
                        int g16 = (col & 63) >> 4;
                        int pp = (j & 1) ? 2*l4 + 1 : 2*l4;
                        d = g16*16 + 2*pp;
                    } else d = col & 63;
                    *(__half2*)(p + d) = __floats2half2_rn(v0, v1);
                }
            }
        }
    }
}

__global__ __launch_bounds__(256, 2) void gemm_qkv(
    const float* __restrict__ bq, const float* __restrict__ bk, const float* __restrict__ bv)
{
    if (blockIdx.z == 0)      gemm_body(g_XhQ, g_WhQ, bq, g_Qp, 1);
    else if (blockIdx.z == 1) gemm_body(g_XhK, g_WhK, bk, g_Kp, 1);
    else                      gemm_body(g_XhV, g_WhV, bv, g_Vp, 0);
}

__global__ __launch_bounds__(256, 2) void gemm_out_h(
    const float* __restrict__ bo, float* __restrict__ out)
{
    gemm_body(g_Ctx, g_WhO, bo, out, 2);
}

// ---------------------------------------------------------------------------
// fp16 flash relative-attention (R13 core, unchanged except plain Ctx write):
// 128 thr (4 warps), q-tile 128, k-tiles 64, one-pass, 2 CTAs/SM.
// ---------------------------------------------------------------------------
#define AQS 80
#define AVS 72
#define OFFQ 0              // Q [128][80]; later P [128][80]
#define OFFK 10240          // relk [104][80] / K tile [64][80] / relv [101][64]
#define OFFV 18560          // V [64][72]
#define OFFQD 23168         // QD [128][104] fp16
#define OFFBD 36480         // band [128][100] fp16
#define ATT_SMEM_BYTES (49280*2)
#define C8 0.18033688011112042f   // 0.125 * log2(e)

__global__ __launch_bounds__(128, 2) void attn_h(
    const float* __restrict__ rel_k, const float* __restrict__ rel_v)
{
    extern __shared__ __half sm16[];
    const uint32_t smb = s2u(sm16);
    __half* qdp = sm16 + OFFQD;
    __half* pbd = sm16 + OFFBD;
    const int tid = threadIdx.x;
    const int lane = tid & 31, w = tid >> 5;
    const int grp = lane >> 2, l4 = lane & 3;
    const int bh = blockIdx.y;
    const int q0 = blockIdx.x * 128;
    const size_t base = (size_t)bh * SEQL * DHD;
    int rl[2][2];
    #pragma unroll
    for (int i = 0; i < 2; i++)
        #pragma unroll
        for (int hh = 0; hh < 2; hh++) rl[i][hh] = w*32 + i*16 + hh*8 + grp;

    #pragma unroll
    for (int s = 0; s < 8; s++) {
        int idx = tid + s*128; int r = idx >> 3, c8 = (idx & 7)*8;
        *(uint4*)&sm16[OFFQ + r*AQS + c8] =
            *(const uint4*)(g_Qp + base + (size_t)(q0+r)*DHD + c8);
    }
    #pragma unroll
    for (int s = 0; s < 13; s++) {
        int i = tid + s*128;
        if (i < 104*16) {
            int r = i >> 4, c4 = (i & 15)*4;
            float4 v = make_float4(0.f,0.f,0.f,0.f);
            if (r < NR) v = *(const float4*)(rel_k + r*DHD + c4);
            int g16 = c4 & ~15;
            int u0 = (c4 & 15) >> 1;
            int p0 = (u0 < 4) ? 2*u0 : 2*(u0-4)+1;
            int p1 = (u0+1 < 4) ? 2*(u0+1) : 2*(u0+1-4)+1;
            __half2* dst = (__half2*)&sm16[OFFK + r*AQS + g16];
            dst[p0] = __floats2half2_rn(v.x, v.y);
            dst[p1] = __floats2half2_rn(v.z, v.w);
        }
    }
    __syncthreads();

    unsigned qf[2][4][4];
    #pragma unroll
    for (int i = 0; i < 2; i++)
        #pragma unroll
        for (int c = 0; c < 4; c++) {
            uint2 t0 = *(const uint2*)&sm16[OFFQ + rl[i][0]*AQS + c*16 + 4*l4];
            uint2 t1 = *(const uint2*)&sm16[OFFQ + rl[i][1]*AQS + c*16 + 4*l4];
            qf[i][c][0] = t0.x; qf[i][c][1] = t1.x;
            qf[i][c][2] = t0.y; qf[i][c][3] = t1.y;
        }
    #pragma unroll
    for (int j = 0; j < 13; j++) {
        float c4a[2][4];
        #pragma unroll
        for (int i = 0; i < 2; i++)
            #pragma unroll
            for (int r = 0; r < 4; r++) c4a[i][r] = 0.f;
        #pragma unroll
        for (int c = 0; c < 4; c++) {
            uint2 tb = *(const uint2*)&sm16[OFFK + (j*8+grp)*AQS + c*16 + 4*l4];
            unsigned bf2[2] = {tb.x, tb.y};
            mma_f16(c4a[0], qf[0][c], bf2);
            mma_f16(c4a[1], qf[1][c], bf2);
        }
        int col = j*8 + l4*2;
        #pragma unroll
        for (int i = 0; i < 2; i++) {
            *(__half2*)&qdp[rl[i][0]*104 + col] = __floats2half2_rn(c4a[i][0], c4a[i][1]);
            *(__half2*)&qdp[rl[i][1]*104 + col] = __floats2half2_rn(c4a[i][2], c4a[i][3]);
        }
    }
    __syncthreads();

    {
        unsigned* bw = (unsigned*)pbd;
        #pragma unroll
        for (int s = 0; s < 50; s++) bw[tid + s*128] = 0u;
    }
    float qlC[2][2], qrC[2][2];
    #pragma unroll
    for (int i = 0; i < 2; i++)
        #pragma unroll
        for (int hh = 0; hh < 2; hh++) {
            qlC[i][hh] = __half2float(qdp[rl[i][hh]*104 + 0])   * C8;
            qrC[i][hh] = __half2float(qdp[rl[i][hh]*104 + 100]) * C8;
        }
    __syncthreads();

    float oacc[2][8][4];
    #pragma unroll
    for (int i = 0; i < 2; i++)
        #pragma unroll
        for (int j = 0; j < 8; j++)
            #pragma unroll
            for (int r = 0; r < 4; r++) oacc[i][j][r] = 0.f;
    float lft[2][2] = {{0.f,0.f},{0.f,0.f}}, rgt[2][2] = {{0.f,0.f},{0.f,0.f}};

    uint4 kreg[4], vreg[4];
    #pragma unroll
    for (int s = 0; s < 4; s++) {
        int idx = tid + s*128; int r = idx >> 3, c8 = (idx & 7)*8;
        kreg[s] = *(const uint4*)(g_Kp + base + (size_t)r*DHD + c8);
        vreg[s] = *(const uint4*)(g_Vp + base + (size_t)r*DHD + c8);
    }

    for (int kt = 0; kt < 32; kt++) {
        const int k0 = kt * 64;
        #pragma unroll
        for (int s = 0; s < 4; s++) {
            int idx = tid + s*128; int r = idx >> 3, c8 = (idx & 7)*8;
            *(uint4*)&sm16[OFFK + r*AQS + c8] = kreg[s];
            *(uint4*)&sm16[OFFV + r*AVS + c8] = vreg[s];
        }
        __syncthreads();
        if (kt + 1 < 32) {
            #pragma unroll
            for (int s = 0; s < 4; s++) {
                int idx = tid + s*128; int r = idx >> 3, c8 = (idx & 7)*8;
                size_t g = base + (size_t)(k0 + 64 + r)*DHD + c8;
                kreg[s] = *(const uint4*)(g_Kp + g);
                vreg[s] = *(const uint4*)(g_Vp + g);
            }
        }

        const int dq = k0 - q0;
        const bool nearT = (dq >= -64 && dq <= 128);
        const bool leftT = dq < 0;

        #pragma unroll
        for (int j = 0; j < 8; j++) {
            float sfr[2][4];
            #pragma unroll
            for (int i = 0; i < 2; i++)
                #pragma unroll
                for (int r = 0; r < 4; r++) sfr[i][r] = 0.f;
            #pragma unroll
            for (int c = 0; c < 4; c++) {
                uint2 tb = *(const uint2*)&sm16[OFFK + (j*8+grp)*AQS + c*16 + 4*l4];
                unsigned bf2[2] = {tb.x, tb.y};
                mma_f16(sfr[0], qf[0][c], bf2);
                mma_f16(sfr[1], qf[1][c], bf2);
            }
            const int po = (j>>1)*16 + ((j&1) ? 4*l4+2 : 4*l4);
            if (nearT) {
                #pragma unroll
                for (int i = 0; i < 2; i++)
                    #pragma unroll
                    for (int hh = 0; hh < 2; hh++) {
                        int rr = rl[i][hh];
                        float pp[2];
                        #pragma unroll
                        for (int par = 0; par < 2; par++) {
                            int col = j*8 + l4*2 + par;
                            int dlt = k0 + col - (q0 + rr);
                            int ix = min(max(dlt, -50), 50) + 50;
                            float qd = __half2float(qdp[rr*104 + ix]);
                            float pv = exp2f((sfr[i][hh*2+par] + qd) * C8);
                            if (dlt <= -50)     lft[i][hh] += pv;
                            else if (dlt >= 50) rgt[i][hh] += pv;
                            else pbd[rr*100 + dlt + 49] = __float2half(pv);
                            pp[par] = pv;
                        }
                        *(__half2*)&sm16[OFFQ + rr*AQS + po] = __floats2half2_rn(pp[0], pp[1]);
                    }
            } else {
                #pragma unroll
                for (int i = 0; i < 2; i++)
                    #pragma unroll
                    for (int hh = 0; hh < 2; hh++) {
                        int rr = rl[i][hh];
                        float qc = leftT ? qlC[i][hh] : qrC[i][hh];
                        float pv0 = exp2f(fmaf(sfr[i][hh*2+0], C8, qc));
                        float pv1 = exp2f(fmaf(sfr[i][hh*2+1], C8, qc));
                        if (leftT) lft[i][hh] += pv0 + pv1;
                        else       rgt[i][hh] += pv0 + pv1;
                        *(__half2*)&sm16[OFFQ + rr*AQS + po] = __floats2half2_rn(pv0, pv1);
                    }
            }
        }
        __syncwarp();

        #pragma unroll
        for (int c = 0; c < 4; c++) {
            unsigned af[2][4];
            #pragma unroll
            for (int i = 0; i < 2; i++) {
                uint2 t0 = *(const uint2*)&sm16[OFFQ + rl[i][0]*AQS + c*16 + 4*l4];
                uint2 t1 = *(const uint2*)&sm16[OFFQ + rl[i][1]*AQS + c*16 + 4*l4];
                af[i][0] = t0.x; af[i][1] = t1.x; af[i][2] = t0.y; af[i][3] = t1.y;
            }
            #pragma unroll
            for (int jj = 0; jj < 8; jj += 2) {
                unsigned r0, r1, r2, r3;
                int mm = lane >> 3, rs = lane & 7;
                uint32_t ad = smb + 2u*(OFFV + (c*16 + (mm&1)*8 + rs)*AVS + (jj + (mm>>1))*8);
                ldsm_x4_trans(r0, r1, r2, r3, ad);
                unsigned b0[2] = {r0, r1}, b1[2] = {r2, r3};
                mma_f16(oacc[0][jj],   af[0], b0);
                mma_f16(oacc[0][jj+1], af[0], b1);
                mma_f16(oacc[1][jj],   af[1], b0);
                mma_f16(oacc[1][jj+1], af[1], b1);
            }
        }
        __syncthreads();
    }

    #pragma unroll
    for (int i = 0; i < 2; i++)
        #pragma unroll
        for (int hh = 0; hh < 2; hh++) {
            lft[i][hh] += __shfl_xor_sync(0xffffffffu, lft[i][hh], 1);
            lft[i][hh] += __shfl_xor_sync(0xffffffffu, lft[i][hh], 2);
            rgt[i][hh] += __shfl_xor_sync(0xffffffffu, rgt[i][hh], 1);
            rgt[i][hh] += __shfl_xor_sync(0xffffffffu, rgt[i][hh], 2);
        }

    #pragma unroll
    for (int s = 0; s < 13; s++) {
        int i = tid + s*128;
        if (i < NR*16) {
            int r = i >> 4, c4 = (i & 15)*4;
            float4 v = *(const float4*)(rel_v + r*DHD + c4);
            __half2* dst = (__half2*)&sm16[OFFK + r*64 + c4];
            dst[0] = __floats2half2_rn(v.x, v.y);
            dst[1] = __floats2half2_rn(v.z, v.w);
        }
    }
    __syncthreads();

    float w2a[2][8][4];
    #pragma unroll
    for (int i = 0; i < 2; i++)
        #pragma unroll
        for (int j = 0; j < 8; j++)
            #pragma unroll
            for (int r = 0; r < 4; r++) w2a[i][j][r] = 0.f;
    float bsum[2][2] = {{0.f,0.f},{0.f,0.f}};
    for (int bnd = 0; bnd < 99; bnd++) {
        float pv[2][2];
        #pragma unroll
        for (int i = 0; i < 2; i++)
            #pragma unroll
            for (int hh = 0; hh < 2; hh++) {
                pv[i][hh] = __half2float(pbd[rl[i][hh]*100 + bnd]);
                bsum[i][hh] += pv[i][hh];
            }
        const __half* rv = &sm16[OFFK + (bnd+1)*64 + l4*2];
        #pragma unroll
        for (int j = 0; j < 8; j++) {
            float2 rr = __half22float2(*(const __half2*)&rv[j*8]);
            #pragma unroll
            for (int i = 0; i < 2; i++) {
                w2a[i][j][0] += pv[i][0]*rr.x; w2a[i][j][1] += pv[i][0]*rr.y;
                w2a[i][j][2] += pv[i][1]*rr.x; w2a[i][j][3] += pv[i][1]*rr.y;
            }
        }
    }
    {
        const __half* rvL = &sm16[OFFK + 0*64   + l4*2];
        const __half* rvR = &sm16[OFFK + 100*64 + l4*2];
        #pragma unroll
        for (int j = 0; j < 8; j++) {
            float2 L = __half22float2(*(const __half2*)&rvL[j*8]);
            float2 R = __half22float2(*(const __half2*)&rvR[j*8]);
            #pragma unroll
            for (int i = 0; i < 2; i++) {
                w2a[i][j][0] += lft[i][0]*L.x + rgt[i][0]*R.x;
                w2a[i][j][1] += lft[i][0]*L.y + rgt[i][0]*R.y;
                w2a[i][j][2] += lft[i][1]*L.x + rgt[i][1]*R.x;
                w2a[i][j][3] += lft[i][1]*L.y + rgt[i][1]*R.y;
            }
        }
    }

    // Ctx: plain fp16 (canonical for ldmatrix out-GEMM)
    const int b = bh / NH, h = bh % NH;
    float inv[2][2];
    #pragma unroll
    for (int i = 0; i < 2; i++)
        #pragma unroll
        for (int hh = 0; hh < 2; hh++)
            inv[i][hh] = 1.f / (lft[i][hh] + rgt[i][hh] + bsum[i][hh]);
    #pragma unroll
    for (int i = 0; i < 2; i++)
        #pragma unroll
        for (int j = 0; j < 8; j++) {
            int dcol = j*8 + l4*2;
            size_t o0 = ((size_t)(b*SEQL + q0 + rl[i][0]))*HIDD + h*DHD + dcol;
            size_t o1 = ((size_t)(b*SEQL + q0 + rl[i][1]))*HIDD + h*DHD + dcol;
            *(__half2*)&g_Ctx[o0] = __floats2half2_rn((oacc[i][j][0] + w2a[i][j][0]) * inv[i][0],
                                                      (oacc[i][j][1] + w2a[i][j][1]) * inv[i][0]);
            *(__half2*)&g_Ctx[o1] = __floats2half2_rn((oacc[i][j][2] + w2a[i][j][2]) * inv[i][1],
                                                      (oacc[i][j][3] + w2a[i][j][3]) * inv[i][1]);
        }
}

// ---------------------------------------------------------------------------
extern "C" void kernel_launch(void* const* d_in, const int* in_sizes, int n_in,
                              void* d_out, int out_size)
{
    const float* query = (const float*)d_in[0];
    const float* key   = (const float*)d_in[1];
    const float* value = (const float*)d_in[2];
    const float* Wq    = (const float*)d_in[3];
    const float* bq    = (const float*)d_in[4];
    const float* Wk    = (const float*)d_in[5];
    const float* bk    = (const float*)d_in[6];
    const float* Wv    = (const float*)d_in[7];
    const float* bv    = (const float*)d_in[8];
    const float* Wo    = (const float*)d_in[9];
    const float* bo    = (const float*)d_in[10];
    const float* rel_k = (const float*)d_in[11];
    const float* rel_v = (const float*)d_in[12];
    float* out = (float*)d_out;

    dim3 gp((SEQL*BATCH*HIDD/8 + 255)/256, 7);
    preh<<<gp, 256>>>(query, key, value, Wq, Wk, Wv, Wo);

    dim3 gq(32, 8, 3);
    gemm_qkv<<<gq, 256>>>(bq, bk, bv);

    cudaFuncSetAttribute(attn_h, cudaFuncAttributeMaxDynamicSharedMemorySize,
                         ATT_SMEM_BYTES);
    dim3 ga(SEQL / 128, BATCH * NH);
    attn_h<<<ga, 128, ATT_SMEM_BYTES>>>(rel_k, rel_v);

    dim3 gg(32, 8);
    gemm_out_h<<<gg, 256>>>(bo, out);
}